// round 1
// baseline (speedup 1.0000x reference)
#include <cuda_runtime.h>
#include <cuda_bf16.h>
#include <math.h>

// ---------------------------------------------------------------------------
// Mamba block forward, fp32 SIMT baseline.
// Pipeline: rmsnorm -> in_proj GEMM -> conv+silu -> x_proj GEMM ->
//           dt_proj GEMM (+softplus) -> selective scan (+silu(z) gate) ->
//           out_proj GEMM (+residual)
// ---------------------------------------------------------------------------

#define BATCH   2
#define SEQ     1024
#define DMODEL  1024
#define DINNER  2048
#define DSTATE  16
#define DTRANK  64
#define DCONV   4
#define NTOK    (BATCH * SEQ)        // 2048 tokens
#define XPROJ_N (DTRANK + 2 * DSTATE) // 96

// Scratch (static device allocations; no runtime alloc allowed)
__device__ float g_h[NTOK * DMODEL];          //  8 MB  rmsnorm output
__device__ float g_xz[NTOK * 2 * DINNER];     // 32 MB  in_proj output (xc | z)
__device__ float g_xs[NTOK * DINNER];         // 16 MB  conv+silu output
__device__ float g_xdbl[NTOK * XPROJ_N];      // .75 MB x_proj output (dt_r|B|C)
__device__ float g_dt[NTOK * DINNER];         // 16 MB  softplus(dt)
__device__ float g_y[NTOK * DINNER];          // 16 MB  scan output (gated)

// ---------------------------------------------------------------------------
// RMSNorm: one block per token row (1024 elems), 256 threads, float4.
// ---------------------------------------------------------------------------
__global__ __launch_bounds__(256) void rmsnorm_kernel(
    const float* __restrict__ x, const float* __restrict__ w,
    float* __restrict__ h)
{
    int row = blockIdx.x;
    int tid = threadIdx.x;
    const float4* xr = reinterpret_cast<const float4*>(x + (size_t)row * DMODEL);
    float4 v = xr[tid];
    float ss = v.x * v.x + v.y * v.y + v.z * v.z + v.w * v.w;

    // block reduce
    __shared__ float red[8];
    #pragma unroll
    for (int o = 16; o > 0; o >>= 1) ss += __shfl_xor_sync(0xffffffffu, ss, o);
    if ((tid & 31) == 0) red[tid >> 5] = ss;
    __syncthreads();
    float tot;
    if (tid < 32) {
        float t = (tid < 8) ? red[tid] : 0.f;
        #pragma unroll
        for (int o = 4; o > 0; o >>= 1) t += __shfl_xor_sync(0xffffffffu, t, o);
        if (tid == 0) red[0] = t;
    }
    __syncthreads();
    tot = red[0];
    float scale = rsqrtf(tot * (1.0f / DMODEL) + 1e-5f);

    const float4* wr = reinterpret_cast<const float4*>(w);
    float4 wv = wr[tid];
    float4 o;
    o.x = v.x * scale * wv.x;
    o.y = v.y * scale * wv.y;
    o.z = v.z * scale * wv.z;
    o.w = v.w * scale * wv.w;
    reinterpret_cast<float4*>(h + (size_t)row * DMODEL)[tid] = o;
}

// ---------------------------------------------------------------------------
// SGEMM (NT): C[M,N] = A[M,K] * B[N,K]^T   (both K-contiguous)
// 128x128 tile, BK=16, 256 threads, 8x8 per thread.
// EPI: 0=none, 1=softplus(acc+bias[n]), 2=acc+res[m,n]
// Requires: M % 128 == 0, K % 16 == 0. N arbitrary (guarded).
// ---------------------------------------------------------------------------
#define BM 128
#define BN 128
#define BKK 16

template<int EPI>
__global__ __launch_bounds__(256) void sgemm_nt(
    const float* __restrict__ A, int lda,
    const float* __restrict__ B, int ldb,
    float* __restrict__ C, int ldc,
    int M, int N, int K,
    const float* __restrict__ bias,
    const float* __restrict__ res, int ldres)
{
    __shared__ float As[BKK][BM];
    __shared__ float Bs[BKK][BN];

    int tid = threadIdx.x;
    int bRow = blockIdx.y * BM;
    int bCol = blockIdx.x * BN;
    int tx = tid & 15;   // N direction
    int ty = tid >> 4;   // M direction

    float acc[8][8];
    #pragma unroll
    for (int i = 0; i < 8; i++)
        #pragma unroll
        for (int j = 0; j < 8; j++) acc[i][j] = 0.f;

    for (int kt = 0; kt < K; kt += BKK) {
        #pragma unroll
        for (int r = 0; r < 2; r++) {
            int idx = tid + r * 256;
            int row = idx >> 2;          // 0..127
            int kq  = (idx & 3) << 2;    // 0,4,8,12
            float4 va = *reinterpret_cast<const float4*>(
                &A[(size_t)(bRow + row) * lda + kt + kq]);
            As[kq + 0][row] = va.x; As[kq + 1][row] = va.y;
            As[kq + 2][row] = va.z; As[kq + 3][row] = va.w;
            int col = bCol + row;
            float4 vb = make_float4(0.f, 0.f, 0.f, 0.f);
            if (col < N)
                vb = *reinterpret_cast<const float4*>(
                    &B[(size_t)col * ldb + kt + kq]);
            Bs[kq + 0][row] = vb.x; Bs[kq + 1][row] = vb.y;
            Bs[kq + 2][row] = vb.z; Bs[kq + 3][row] = vb.w;
        }
        __syncthreads();

        #pragma unroll
        for (int k = 0; k < BKK; k++) {
            float ar[8], br[8];
            #pragma unroll
            for (int i = 0; i < 8; i++) ar[i] = As[k][ty * 8 + i];
            #pragma unroll
            for (int j = 0; j < 8; j++) br[j] = Bs[k][tx * 8 + j];
            #pragma unroll
            for (int i = 0; i < 8; i++)
                #pragma unroll
                for (int j = 0; j < 8; j++)
                    acc[i][j] = fmaf(ar[i], br[j], acc[i][j]);
        }
        __syncthreads();
    }

    #pragma unroll
    for (int i = 0; i < 8; i++) {
        int row = bRow + ty * 8 + i;
        #pragma unroll
        for (int j = 0; j < 8; j++) {
            int col = bCol + tx * 8 + j;
            if (col < N) {
                float v = acc[i][j];
                if (EPI == 1) {
                    v += bias[col];
                    v = (v > 20.f) ? v : log1pf(expf(v));
                } else if (EPI == 2) {
                    v += res[(size_t)row * ldres + col];
                }
                C[(size_t)row * ldc + col] = v;
            }
        }
    }
}

// ---------------------------------------------------------------------------
// Depthwise causal conv (width 4) + SiLU.
// xc is the first DINNER columns of g_xz (row stride 2*DINNER).
// ---------------------------------------------------------------------------
__global__ __launch_bounds__(256) void conv_silu_kernel(
    const float* __restrict__ xz,
    const float* __restrict__ conv_w, const float* __restrict__ conv_b,
    float* __restrict__ xs)
{
    int idx = blockIdx.x * 256 + threadIdx.x;   // over NTOK * DINNER
    if (idx >= NTOK * DINNER) return;
    int trow = idx >> 11;        // token row (b*SEQ + l), DINNER=2048
    int d    = idx & 2047;
    int l    = trow & (SEQ - 1);

    float acc = conv_b[d];
    #pragma unroll
    for (int k = 0; k < DCONV; k++) {
        int li = l + k - (DCONV - 1);
        if (li >= 0) {
            float xv = xz[(size_t)(trow + li - l) * (2 * DINNER) + d];
            acc = fmaf(conv_w[d * DCONV + k], xv, acc);
        }
    }
    // silu
    float s = acc / (1.f + __expf(-acc));
    xs[idx] = s;
}

// ---------------------------------------------------------------------------
// Selective scan. One warp = 2 channels; lanes 0-15 / 16-31 hold the 16
// states of each channel. Sequential over L, shfl-reduce over states.
// Output is gated by silu(z) here.
// ---------------------------------------------------------------------------
__global__ __launch_bounds__(256) void scan_kernel(
    const float* __restrict__ dt, const float* __restrict__ xs,
    const float* __restrict__ xdbl, const float* __restrict__ xz,
    const float* __restrict__ A_log, const float* __restrict__ Dp,
    float* __restrict__ y)
{
    int warp = threadIdx.x >> 5;
    int lane = threadIdx.x & 31;
    int chPair = blockIdx.x * 8 + warp;          // 0..2047
    int ch = chPair * 2 + (lane >> 4);           // 0..4095
    int b = ch >> 11;                            // / DINNER
    int d = ch & 2047;
    int n = lane & 15;

    float a  = -expf(A_log[d * DSTATE + n]);
    float Dv = Dp[d];
    float s = 0.f;
    int rowBase = b * SEQ;

    for (int t = 0; t < SEQ; t++) {
        int row = rowBase + t;
        float dtv = dt[(size_t)row * DINNER + d];
        float xsv = xs[(size_t)row * DINNER + d];
        float Bv  = xdbl[(size_t)row * XPROJ_N + DTRANK + n];
        float Cv  = xdbl[(size_t)row * XPROJ_N + DTRANK + DSTATE + n];

        float dA = __expf(dtv * a);
        s = fmaf(dA, s, dtv * xsv * Bv);

        float p = s * Cv;
        p += __shfl_xor_sync(0xffffffffu, p, 8);
        p += __shfl_xor_sync(0xffffffffu, p, 4);
        p += __shfl_xor_sync(0xffffffffu, p, 2);
        p += __shfl_xor_sync(0xffffffffu, p, 1);

        if (n == 0) {
            float zv = xz[(size_t)row * (2 * DINNER) + DINNER + d];
            float gate = zv / (1.f + __expf(-zv));
            y[(size_t)row * DINNER + d] = (p + Dv * xsv) * gate;
        }
    }
}

// ---------------------------------------------------------------------------
// Launch
// ---------------------------------------------------------------------------
extern "C" void kernel_launch(void* const* d_in, const int* in_sizes, int n_in,
                              void* d_out, int out_size)
{
    const float* x         = (const float*)d_in[0];
    const float* norm_w    = (const float*)d_in[1];
    const float* in_proj_w = (const float*)d_in[2];
    const float* conv_w    = (const float*)d_in[3];
    const float* conv_b    = (const float*)d_in[4];
    const float* x_proj_w  = (const float*)d_in[5];
    const float* dt_proj_w = (const float*)d_in[6];
    const float* dt_proj_b = (const float*)d_in[7];
    const float* A_log     = (const float*)d_in[8];
    const float* Dp        = (const float*)d_in[9];
    const float* out_proj_w= (const float*)d_in[10];
    float* out = (float*)d_out;

    float *ph, *pxz, *pxs, *pxdbl, *pdt, *py;
    cudaGetSymbolAddress((void**)&ph,    g_h);
    cudaGetSymbolAddress((void**)&pxz,   g_xz);
    cudaGetSymbolAddress((void**)&pxs,   g_xs);
    cudaGetSymbolAddress((void**)&pxdbl, g_xdbl);
    cudaGetSymbolAddress((void**)&pdt,   g_dt);
    cudaGetSymbolAddress((void**)&py,    g_y);

    // 1) RMSNorm
    rmsnorm_kernel<<<NTOK, 256>>>(x, norm_w, ph);

    // 2) in_proj: [2048,1024] x [4096,1024]^T -> [2048,4096]
    {
        dim3 grid((2 * DINNER) / BN, NTOK / BM);
        sgemm_nt<0><<<grid, 256>>>(ph, DMODEL, in_proj_w, DMODEL,
                                   pxz, 2 * DINNER,
                                   NTOK, 2 * DINNER, DMODEL,
                                   nullptr, nullptr, 0);
    }

    // 3) conv + silu
    conv_silu_kernel<<<(NTOK * DINNER) / 256, 256>>>(pxz, conv_w, conv_b, pxs);

    // 4) x_proj: [2048,2048] x [96,2048]^T -> [2048,96]
    {
        dim3 grid(1, NTOK / BM);
        sgemm_nt<0><<<grid, 256>>>(pxs, DINNER, x_proj_w, DINNER,
                                   pxdbl, XPROJ_N,
                                   NTOK, XPROJ_N, DINNER,
                                   nullptr, nullptr, 0);
    }

    // 5) dt_proj + softplus: [2048,64] (lda=96) x [2048,64]^T -> [2048,2048]
    {
        dim3 grid(DINNER / BN, NTOK / BM);
        sgemm_nt<1><<<grid, 256>>>(pxdbl, XPROJ_N, dt_proj_w, DTRANK,
                                   pdt, DINNER,
                                   NTOK, DINNER, DTRANK,
                                   dt_proj_b, nullptr, 0);
    }

    // 6) selective scan (+ silu(z) gate)
    scan_kernel<<<(BATCH * DINNER) / 16, 256>>>(pdt, pxs, pxdbl, pxz,
                                                A_log, Dp, py);

    // 7) out_proj + residual: [2048,2048] x [1024,2048]^T -> [2048,1024]
    {
        dim3 grid(DMODEL / BN, NTOK / BM);
        sgemm_nt<2><<<grid, 256>>>(py, DINNER, out_proj_w, DINNER,
                                   out, DMODEL,
                                   NTOK, DMODEL, DINNER,
                                   nullptr, x, DMODEL);
    }
}

// round 3
// speedup vs baseline: 1.6421x; 1.6421x over previous
#include <cuda_runtime.h>
#include <cuda_bf16.h>
#include <cstdint>
#include <math.h>

// ---------------------------------------------------------------------------
// Mamba block forward. GEMMs via mma.sync (HMMA bf16, split-precision hi+lo,
// fp32 accum) — base-ISA only (no sm_103a features).
// ---------------------------------------------------------------------------

#define BATCH   2
#define SEQ     1024
#define DMODEL  1024
#define DINNER  2048
#define DSTATE  16
#define DTRANK  64
#define DCONV   4
#define NTOK    (BATCH * SEQ)
#define XPROJ_N (DTRANK + 2 * DSTATE)   // 96
#define XSPLIT  16                      // split-K factor for x_proj

typedef __nv_bfloat16 bf16;

// fp32 scratch
__device__ __align__(256) float g_xz[NTOK * 2 * DINNER];
__device__ __align__(256) float g_xs[NTOK * DINNER];
__device__ __align__(256) float g_xdbl[NTOK * XPROJ_N];
__device__ __align__(256) float g_dt[NTOK * DINNER];
__device__ __align__(256) float g_part[XSPLIT * NTOK * XPROJ_N];

// bf16 hi/lo scratch (split precision)
__device__ __align__(256) bf16 g_wih[2 * DINNER * DMODEL], g_wil[2 * DINNER * DMODEL];
__device__ __align__(256) bf16 g_wxh[XPROJ_N * DINNER],    g_wxl[XPROJ_N * DINNER];
__device__ __align__(256) bf16 g_wdh[DINNER * DTRANK],     g_wdl[DINNER * DTRANK];
__device__ __align__(256) bf16 g_woh[DMODEL * DINNER],     g_wol[DMODEL * DINNER];
__device__ __align__(256) bf16 g_hh[NTOK * DMODEL],        g_hl[NTOK * DMODEL];
__device__ __align__(256) bf16 g_xsh[NTOK * DINNER],       g_xsl[NTOK * DINNER];
__device__ __align__(256) bf16 g_xdh[NTOK * XPROJ_N],      g_xdl[NTOK * XPROJ_N];
__device__ __align__(256) bf16 g_yh[NTOK * DINNER],        g_yl[NTOK * DINNER];

// ---------------------------------------------------------------------------
// helpers
// ---------------------------------------------------------------------------
__device__ __forceinline__ uint32_t smem_u32(const void* p) {
    uint32_t a;
    asm("{ .reg .u64 t; cvta.to.shared.u64 t, %1; cvt.u32.u64 %0, t; }"
        : "=r"(a) : "l"(p));
    return a;
}
__device__ __forceinline__ void ldm_x4(uint32_t& r0, uint32_t& r1,
                                       uint32_t& r2, uint32_t& r3, uint32_t a) {
    asm volatile("ldmatrix.sync.aligned.m8n8.x4.shared.b16 {%0,%1,%2,%3}, [%4];"
                 : "=r"(r0), "=r"(r1), "=r"(r2), "=r"(r3) : "r"(a));
}
__device__ __forceinline__ void mma16816(float* d, const uint32_t* a,
                                         const uint32_t* b) {
    asm volatile(
        "mma.sync.aligned.m16n8k16.row.col.f32.bf16.bf16.f32 "
        "{%0,%1,%2,%3}, {%4,%5,%6,%7}, {%8,%9}, {%0,%1,%2,%3};"
        : "+f"(d[0]), "+f"(d[1]), "+f"(d[2]), "+f"(d[3])
        : "r"(a[0]), "r"(a[1]), "r"(a[2]), "r"(a[3]), "r"(b[0]), "r"(b[1]));
}
__device__ __forceinline__ void cp16(uint32_t dst, const void* src, int sz) {
    asm volatile("cp.async.cg.shared.global [%0], [%1], 16, %2;"
                 :: "r"(dst), "l"(src), "r"(sz) : "memory");
}
#define CP_COMMIT() asm volatile("cp.async.commit_group;" ::: "memory")
#define CP_WAIT(n)  asm volatile("cp.async.wait_group %0;" :: "n"(n) : "memory")

__device__ __forceinline__ uint32_t pack2(bf16 a, bf16 b) {
    return ((uint32_t)__bfloat16_as_ushort(b) << 16) | __bfloat16_as_ushort(a);
}
__device__ __forceinline__ void split1(float v, bf16& h, bf16& l) {
    h = __float2bfloat16(v);
    l = __float2bfloat16(v - __bfloat162float(h));
}
__device__ __forceinline__ void split4(float4 v, uint2& hi, uint2& lo) {
    bf16 h0, l0, h1, l1, h2, l2, h3, l3;
    split1(v.x, h0, l0); split1(v.y, h1, l1);
    split1(v.z, h2, l2); split1(v.w, h3, l3);
    hi.x = pack2(h0, h1); hi.y = pack2(h2, h3);
    lo.x = pack2(l0, l1); lo.y = pack2(l2, l3);
}

// ---------------------------------------------------------------------------
// HMMA GEMM (NT): C[M,N] = A[M,K]·B[N,K]^T with A,B = hi+lo bf16.
// CTA 128x128, K-chunk 64, double-buffered cp.async, 256 threads (8 warps,
// warp tile 64x32). 3 mma passes: Ah·Bh + Ah·Bl + Al·Bh.
// EPI: 0 none, 1 softplus(acc+bias[n]), 2 acc+res[m,n]
// gridDim.z = split-K count; Ksplit = K per split (mult of 64), M%128==0.
// ---------------------------------------------------------------------------
#define STAGE_SZ 65536
#define GEMM_SMEM (2 * STAGE_SZ)

template<int EPI>
__global__ void __launch_bounds__(256, 1) mma_gemm(
    const bf16* __restrict__ Ah, const bf16* __restrict__ Al, int lda,
    const bf16* __restrict__ Bh, const bf16* __restrict__ Bl, int ldb,
    float* __restrict__ C, int ldc, int N, int Ksplit, long partStride,
    const float* __restrict__ bias, const float* __restrict__ res, int ldres)
{
    extern __shared__ char smem[];
    const uint32_t sb = smem_u32(smem);
    const int tid = threadIdx.x;
    const int bRow = blockIdx.y * 128, bCol = blockIdx.x * 128;
    const int kbase = blockIdx.z * Ksplit;
    C += (long)blockIdx.z * partStride;
    const int nChunks = Ksplit >> 6;

    const int wid = tid >> 5, l = tid & 31;
    const int wm = (wid >> 2) * 64, wn = (wid & 3) * 32;

    float acc[4][4][4];
    #pragma unroll
    for (int a = 0; a < 4; a++)
        #pragma unroll
        for (int b = 0; b < 4; b++)
            #pragma unroll
            for (int c = 0; c < 4; c++) acc[a][b][c] = 0.f;

    // ---- stage loader (A hi/lo + B hi/lo, SW128-style swizzle) ----
    auto loadStage = [&](int c) {
        const int kt = kbase + (c << 6);
        const uint32_t base = sb + (c & 1) * STAGE_SZ;
        #pragma unroll
        for (int it = 0; it < 4; it++) {
            int lin = it * 256 + tid;          // 0..1023
            int row = lin >> 3, ch = lin & 7;  // 128 rows x 8 chunks(16B)
            uint32_t d = base + row * 128 + (((ch ^ (row & 7)) << 4));
            size_t aoff = (size_t)(bRow + row) * lda + kt + ch * 8;
            cp16(d,         Ah + aoff, 16);
            cp16(d + 16384, Al + aoff, 16);
            int bn = bCol + row;
            int ok = (bn < N) ? 16 : 0;
            size_t boff = (size_t)(bn < N ? bn : 0) * ldb + kt + ch * 8;
            cp16(d + 32768, Bh + boff, ok);
            cp16(d + 49152, Bl + boff, ok);
        }
        CP_COMMIT();
    };

    loadStage(0);
    for (int c = 0; c < nChunks; c++) {
        if (c + 1 < nChunks) { loadStage(c + 1); CP_WAIT(1); }
        else                 { CP_WAIT(0); }
        __syncthreads();
        const uint32_t st = sb + (c & 1) * STAGE_SZ;

        uint32_t baseA[4]; int r7A[4];
        #pragma unroll
        for (int mi = 0; mi < 4; mi++) {
            int r = wm + mi * 16 + (l & 15);
            baseA[mi] = st + r * 128;
            r7A[mi] = r & 7;
        }
        const int hkA = l >> 4;            // 0/1: k half
        const int matb = l >> 3;
        const int rB0 = wn + (l & 7) + ((matb >> 1) << 3);
        const int hkB = matb & 1;

        #pragma unroll
        for (int ks = 0; ks < 4; ks++) {
            uint32_t Ahf[4][4], Alf[4][4], Bhf[4][2], Blf[4][2];
            #pragma unroll
            for (int mi = 0; mi < 4; mi++) {
                int ck = 2 * ks + hkA;
                uint32_t ad = baseA[mi] + ((ck ^ r7A[mi]) << 4);
                ldm_x4(Ahf[mi][0], Ahf[mi][1], Ahf[mi][2], Ahf[mi][3], ad);
                ldm_x4(Alf[mi][0], Alf[mi][1], Alf[mi][2], Alf[mi][3], ad + 16384);
            }
            #pragma unroll
            for (int ng = 0; ng < 2; ng++) {
                int r = rB0 + ng * 16;
                int ck = 2 * ks + hkB;
                uint32_t ad = st + 32768 + r * 128 + ((ck ^ (r & 7)) << 4);
                uint32_t t0, t1, t2, t3;
                ldm_x4(t0, t1, t2, t3, ad);
                Bhf[ng*2][0] = t0; Bhf[ng*2][1] = t1;
                Bhf[ng*2+1][0] = t2; Bhf[ng*2+1][1] = t3;
                ldm_x4(t0, t1, t2, t3, ad + 16384);
                Blf[ng*2][0] = t0; Blf[ng*2][1] = t1;
                Blf[ng*2+1][0] = t2; Blf[ng*2+1][1] = t3;
            }
            #pragma unroll
            for (int mi = 0; mi < 4; mi++)
                #pragma unroll
                for (int ni = 0; ni < 4; ni++) {
                    mma16816(acc[mi][ni], Ahf[mi], Bhf[ni]);
                    mma16816(acc[mi][ni], Ahf[mi], Blf[ni]);
                    mma16816(acc[mi][ni], Alf[mi], Bhf[ni]);
                }
        }
        __syncthreads();
    }

    // ---- epilogue ----
    #pragma unroll
    for (int mi = 0; mi < 4; mi++) {
        #pragma unroll
        for (int h2 = 0; h2 < 2; h2++) {
            int row = bRow + wm + mi * 16 + h2 * 8 + (l >> 2);
            #pragma unroll
            for (int ni = 0; ni < 4; ni++) {
                int col = bCol + wn + ni * 8 + (l & 3) * 2;
                if (col < N) {
                    float v0 = acc[mi][ni][h2 * 2 + 0];
                    float v1 = acc[mi][ni][h2 * 2 + 1];
                    if (EPI == 1) {
                        v0 += bias[col];     v1 += bias[col + 1];
                        v0 = (v0 > 20.f) ? v0 : log1pf(expf(v0));
                        v1 = (v1 > 20.f) ? v1 : log1pf(expf(v1));
                    } else if (EPI == 2) {
                        const float* rr = res + (size_t)row * ldres + col;
                        v0 += rr[0]; v1 += rr[1];
                    }
                    float2 o = make_float2(v0, v1);
                    *reinterpret_cast<float2*>(C + (size_t)row * ldc + col) = o;
                }
            }
        }
    }
}

// ---------------------------------------------------------------------------
// weight fp32 -> bf16 hi/lo
// ---------------------------------------------------------------------------
__global__ __launch_bounds__(256) void convert_w(
    const float* __restrict__ w, bf16* __restrict__ hi, bf16* __restrict__ lo,
    int n4)
{
    int i = blockIdx.x * 256 + threadIdx.x;
    if (i >= n4) return;
    float4 v = reinterpret_cast<const float4*>(w)[i];
    uint2 h, l;
    split4(v, h, l);
    reinterpret_cast<uint2*>(hi)[i] = h;
    reinterpret_cast<uint2*>(lo)[i] = l;
}

// ---------------------------------------------------------------------------
// RMSNorm -> bf16 hi/lo
// ---------------------------------------------------------------------------
__global__ __launch_bounds__(256) void rmsnorm_kernel(
    const float* __restrict__ x, const float* __restrict__ w,
    bf16* __restrict__ hh, bf16* __restrict__ hl)
{
    int row = blockIdx.x;
    int tid = threadIdx.x;
    float4 v = reinterpret_cast<const float4*>(x + (size_t)row * DMODEL)[tid];
    float ss = v.x * v.x + v.y * v.y + v.z * v.z + v.w * v.w;
    __shared__ float red[8];
    #pragma unroll
    for (int o = 16; o > 0; o >>= 1) ss += __shfl_xor_sync(0xffffffffu, ss, o);
    if ((tid & 31) == 0) red[tid >> 5] = ss;
    __syncthreads();
    if (tid < 32) {
        float t = (tid < 8) ? red[tid] : 0.f;
        #pragma unroll
        for (int o = 4; o > 0; o >>= 1) t += __shfl_xor_sync(0xffffffffu, t, o);
        if (tid == 0) red[0] = t;
    }
    __syncthreads();
    float scale = rsqrtf(red[0] * (1.0f / DMODEL) + 1e-5f);
    float4 wv = reinterpret_cast<const float4*>(w)[tid];
    float4 o;
    o.x = v.x * scale * wv.x;  o.y = v.y * scale * wv.y;
    o.z = v.z * scale * wv.z;  o.w = v.w * scale * wv.w;
    uint2 h, l;
    split4(o, h, l);
    reinterpret_cast<uint2*>(hh + (size_t)row * DMODEL)[tid] = h;
    reinterpret_cast<uint2*>(hl + (size_t)row * DMODEL)[tid] = l;
}

// ---------------------------------------------------------------------------
// conv(width4) + SiLU -> fp32 + bf16 hi/lo   (4 channels per thread)
// ---------------------------------------------------------------------------
__global__ __launch_bounds__(256) void conv_silu_kernel(
    const float* __restrict__ xz,
    const float* __restrict__ conv_w, const float* __restrict__ conv_b,
    float* __restrict__ xs, bf16* __restrict__ xsh, bf16* __restrict__ xsl)
{
    int gid = blockIdx.x * 256 + threadIdx.x;  // over NTOK * DINNER/4
    if (gid >= NTOK * (DINNER / 4)) return;
    int trow = gid / (DINNER / 4);
    int d0 = (gid % (DINNER / 4)) * 4;
    int lpos = trow & (SEQ - 1);

    float4 accv = *reinterpret_cast<const float4*>(conv_b + d0);
    float* acc = &accv.x;
    #pragma unroll
    for (int k = 0; k < DCONV; k++) {
        int li = lpos + k - (DCONV - 1);
        if (li >= 0) {
            const float* xp = xz + (size_t)(trow + li - lpos) * (2 * DINNER) + d0;
            #pragma unroll
            for (int q = 0; q < 4; q++)
                acc[q] = fmaf(conv_w[(d0 + q) * DCONV + k], xp[q], acc[q]);
        }
    }
    #pragma unroll
    for (int q = 0; q < 4; q++) acc[q] = acc[q] / (1.f + __expf(-acc[q]));
    size_t base = (size_t)trow * DINNER + d0;
    *reinterpret_cast<float4*>(xs + base) = accv;
    uint2 h, l;
    split4(accv, h, l);
    *reinterpret_cast<uint2*>(xsh + base) = h;
    *reinterpret_cast<uint2*>(xsl + base) = l;
}

// ---------------------------------------------------------------------------
// split-K reduce for x_proj -> fp32 + bf16 hi/lo
// ---------------------------------------------------------------------------
__global__ __launch_bounds__(256) void reduce_xproj(
    const float* __restrict__ part, float* __restrict__ xd,
    bf16* __restrict__ xdh, bf16* __restrict__ xdl)
{
    int idx = blockIdx.x * 256 + threadIdx.x;
    if (idx >= NTOK * XPROJ_N) return;
    float s = 0.f;
    #pragma unroll
    for (int z = 0; z < XSPLIT; z++) s += part[(size_t)z * NTOK * XPROJ_N + idx];
    xd[idx] = s;
    bf16 h, l;
    split1(s, h, l);
    xdh[idx] = h; xdl[idx] = l;
}

// ---------------------------------------------------------------------------
// selective scan + silu(z) gate -> y bf16 hi/lo
// ---------------------------------------------------------------------------
__global__ __launch_bounds__(256) void scan_kernel(
    const float* __restrict__ dt, const float* __restrict__ xs,
    const float* __restrict__ xdbl, const float* __restrict__ xz,
    const float* __restrict__ A_log, const float* __restrict__ Dp,
    bf16* __restrict__ yh, bf16* __restrict__ yl)
{
    int warp = threadIdx.x >> 5;
    int lane = threadIdx.x & 31;
    int chPair = blockIdx.x * 8 + warp;
    int ch = chPair * 2 + (lane >> 4);
    int b = ch >> 11;
    int d = ch & 2047;
    int n = lane & 15;

    float a  = -expf(A_log[d * DSTATE + n]);
    float Dv = Dp[d];
    float s = 0.f;
    int rowBase = b * SEQ;

    for (int t = 0; t < SEQ; t++) {
        int row = rowBase + t;
        float dtv = dt[(size_t)row * DINNER + d];
        float xsv = xs[(size_t)row * DINNER + d];
        float Bv  = xdbl[(size_t)row * XPROJ_N + DTRANK + n];
        float Cv  = xdbl[(size_t)row * XPROJ_N + DTRANK + DSTATE + n];

        float dA = __expf(dtv * a);
        s = fmaf(dA, s, dtv * xsv * Bv);

        float p = s * Cv;
        p += __shfl_xor_sync(0xffffffffu, p, 8);
        p += __shfl_xor_sync(0xffffffffu, p, 4);
        p += __shfl_xor_sync(0xffffffffu, p, 2);
        p += __shfl_xor_sync(0xffffffffu, p, 1);

        if (n == 0) {
            float zv = xz[(size_t)row * (2 * DINNER) + DINNER + d];
            float gate = zv / (1.f + __expf(-zv));
            float val = (p + Dv * xsv) * gate;
            bf16 h, l;
            split1(val, h, l);
            yh[(size_t)row * DINNER + d] = h;
            yl[(size_t)row * DINNER + d] = l;
        }
    }
}

// ---------------------------------------------------------------------------
// Launch
// ---------------------------------------------------------------------------
extern "C" void kernel_launch(void* const* d_in, const int* in_sizes, int n_in,
                              void* d_out, int out_size)
{
    const float* x         = (const float*)d_in[0];
    const float* norm_w    = (const float*)d_in[1];
    const float* in_proj_w = (const float*)d_in[2];
    const float* conv_w    = (const float*)d_in[3];
    const float* conv_b    = (const float*)d_in[4];
    const float* x_proj_w  = (const float*)d_in[5];
    const float* dt_proj_w = (const float*)d_in[6];
    const float* dt_proj_b = (const float*)d_in[7];
    const float* A_log     = (const float*)d_in[8];
    const float* Dp        = (const float*)d_in[9];
    const float* out_proj_w= (const float*)d_in[10];
    float* out = (float*)d_out;

    float *pxz, *pxs, *pxdbl, *pdt, *ppart;
    bf16 *pwih, *pwil, *pwxh, *pwxl, *pwdh, *pwdl, *pwoh, *pwol;
    bf16 *phh, *phl, *pxsh, *pxsl, *pxdh, *pxdl, *pyh, *pyl;
    cudaGetSymbolAddress((void**)&pxz,  g_xz);
    cudaGetSymbolAddress((void**)&pxs,  g_xs);
    cudaGetSymbolAddress((void**)&pxdbl,g_xdbl);
    cudaGetSymbolAddress((void**)&pdt,  g_dt);
    cudaGetSymbolAddress((void**)&ppart,g_part);
    cudaGetSymbolAddress((void**)&pwih, g_wih); cudaGetSymbolAddress((void**)&pwil, g_wil);
    cudaGetSymbolAddress((void**)&pwxh, g_wxh); cudaGetSymbolAddress((void**)&pwxl, g_wxl);
    cudaGetSymbolAddress((void**)&pwdh, g_wdh); cudaGetSymbolAddress((void**)&pwdl, g_wdl);
    cudaGetSymbolAddress((void**)&pwoh, g_woh); cudaGetSymbolAddress((void**)&pwol, g_wol);
    cudaGetSymbolAddress((void**)&phh,  g_hh);  cudaGetSymbolAddress((void**)&phl,  g_hl);
    cudaGetSymbolAddress((void**)&pxsh, g_xsh); cudaGetSymbolAddress((void**)&pxsl, g_xsl);
    cudaGetSymbolAddress((void**)&pxdh, g_xdh); cudaGetSymbolAddress((void**)&pxdl, g_xdl);
    cudaGetSymbolAddress((void**)&pyh,  g_yh);  cudaGetSymbolAddress((void**)&pyl,  g_yl);

    cudaFuncSetAttribute(mma_gemm<0>, cudaFuncAttributeMaxDynamicSharedMemorySize, GEMM_SMEM);
    cudaFuncSetAttribute(mma_gemm<1>, cudaFuncAttributeMaxDynamicSharedMemorySize, GEMM_SMEM);
    cudaFuncSetAttribute(mma_gemm<2>, cudaFuncAttributeMaxDynamicSharedMemorySize, GEMM_SMEM);

    // 0) weight conversion (fp32 -> bf16 hi/lo)
    convert_w<<<(2*DINNER*DMODEL/4 + 255)/256, 256>>>(in_proj_w,  pwih, pwil, 2*DINNER*DMODEL/4);
    convert_w<<<(XPROJ_N*DINNER/4 + 255)/256, 256>>>(x_proj_w,   pwxh, pwxl, XPROJ_N*DINNER/4);
    convert_w<<<(DINNER*DTRANK/4 + 255)/256, 256>>>(dt_proj_w,  pwdh, pwdl, DINNER*DTRANK/4);
    convert_w<<<(DMODEL*DINNER/4 + 255)/256, 256>>>(out_proj_w, pwoh, pwol, DMODEL*DINNER/4);

    // 1) RMSNorm -> h hi/lo
    rmsnorm_kernel<<<NTOK, 256>>>(x, norm_w, phh, phl);

    // 2) in_proj: [2048,1024] x [4096,1024]^T -> xz fp32
    {
        dim3 grid((2 * DINNER) / 128, NTOK / 128, 1);
        mma_gemm<0><<<grid, 256, GEMM_SMEM>>>(
            phh, phl, DMODEL, pwih, pwil, DMODEL,
            pxz, 2 * DINNER, 2 * DINNER, DMODEL, 0, nullptr, nullptr, 0);
    }

    // 3) conv + silu -> xs fp32 + hi/lo
    conv_silu_kernel<<<(NTOK * DINNER / 4) / 256, 256>>>(
        pxz, conv_w, conv_b, pxs, pxsh, pxsl);

    // 4) x_proj split-K=16: [2048,2048] x [96,2048]^T -> partials
    {
        dim3 grid(1, NTOK / 128, XSPLIT);
        mma_gemm<0><<<grid, 256, GEMM_SMEM>>>(
            pxsh, pxsl, DINNER, pwxh, pwxl, DINNER,
            ppart, XPROJ_N, XPROJ_N, DINNER / XSPLIT,
            (long)NTOK * XPROJ_N, nullptr, nullptr, 0);
    }
    reduce_xproj<<<(NTOK * XPROJ_N + 255) / 256, 256>>>(ppart, pxdbl, pxdh, pxdl);

    // 5) dt_proj + softplus: [2048,64](lda=96) x [2048,64]^T -> dt fp32
    {
        dim3 grid(DINNER / 128, NTOK / 128, 1);
        mma_gemm<1><<<grid, 256, GEMM_SMEM>>>(
            pxdh, pxdl, XPROJ_N, pwdh, pwdl, DTRANK,
            pdt, DINNER, DINNER, DTRANK, 0, dt_proj_b, nullptr, 0);
    }

    // 6) selective scan (+ silu(z) gate) -> y hi/lo
    scan_kernel<<<(BATCH * DINNER) / 16, 256>>>(pdt, pxs, pxdbl, pxz,
                                                A_log, Dp, pyh, pyl);

    // 7) out_proj + residual: [2048,2048] x [1024,2048]^T -> out
    {
        dim3 grid(DMODEL / 128, NTOK / 128, 1);
        mma_gemm<2><<<grid, 256, GEMM_SMEM>>>(
            pyh, pyl, DINNER, pwoh, pwol, DINNER,
            out, DMODEL, DMODEL, DINNER, 0, nullptr, x, DMODEL);
    }
}

// round 4
// speedup vs baseline: 5.0326x; 3.0648x over previous
#include <cuda_runtime.h>
#include <cuda_bf16.h>
#include <cstdint>
#include <math.h>

// ---------------------------------------------------------------------------
// Mamba block forward. GEMMs via mma.sync (HMMA bf16 split hi/lo, fp32 accum).
// Scan operates on [channel][time]-transposed activations (float4 per 4 steps).
// ---------------------------------------------------------------------------

#define BATCH   2
#define SEQ     1024
#define DMODEL  1024
#define DINNER  2048
#define DSTATE  16
#define DTRANK  64
#define DCONV   4
#define NTOK    (BATCH * SEQ)
#define XPROJ_N (DTRANK + 2 * DSTATE)   // 96
#define XSPLIT  16

typedef __nv_bfloat16 bf16;

// fp32 scratch
__device__ __align__(256) float g_xz[NTOK * 2 * DINNER];     // in_proj out (xc|z)
__device__ __align__(256) float g_xsT[DINNER * NTOK];        // silu(conv) transposed
__device__ __align__(256) float g_gT[DINNER * NTOK];         // silu(z) transposed
__device__ __align__(256) float g_dtT[DINNER * NTOK];        // softplus(dt) transposed
__device__ __align__(256) float g_bcT[2 * DSTATE * NTOK];    // B,C transposed
__device__ __align__(256) float g_yT[DINNER * NTOK];         // scan out transposed
__device__ __align__(256) float g_part[XSPLIT * NTOK * XPROJ_N];

// bf16 hi/lo scratch
__device__ __align__(256) bf16 g_wih[2 * DINNER * DMODEL], g_wil[2 * DINNER * DMODEL];
__device__ __align__(256) bf16 g_wxh[XPROJ_N * DINNER],    g_wxl[XPROJ_N * DINNER];
__device__ __align__(256) bf16 g_wdh[DINNER * DTRANK],     g_wdl[DINNER * DTRANK];
__device__ __align__(256) bf16 g_woh[DMODEL * DINNER],     g_wol[DMODEL * DINNER];
__device__ __align__(256) bf16 g_hh[NTOK * DMODEL],        g_hl[NTOK * DMODEL];
__device__ __align__(256) bf16 g_xsh[NTOK * DINNER],       g_xsl[NTOK * DINNER];
__device__ __align__(256) bf16 g_xdh[NTOK * XPROJ_N],      g_xdl[NTOK * XPROJ_N];
__device__ __align__(256) bf16 g_yh[NTOK * DINNER],        g_yl[NTOK * DINNER];

// ---------------------------------------------------------------------------
// helpers
// ---------------------------------------------------------------------------
__device__ __forceinline__ uint32_t smem_u32(const void* p) {
    uint32_t a;
    asm("{ .reg .u64 t; cvta.to.shared.u64 t, %1; cvt.u32.u64 %0, t; }"
        : "=r"(a) : "l"(p));
    return a;
}
__device__ __forceinline__ void ldm_x4(uint32_t& r0, uint32_t& r1,
                                       uint32_t& r2, uint32_t& r3, uint32_t a) {
    asm volatile("ldmatrix.sync.aligned.m8n8.x4.shared.b16 {%0,%1,%2,%3}, [%4];"
                 : "=r"(r0), "=r"(r1), "=r"(r2), "=r"(r3) : "r"(a));
}
__device__ __forceinline__ void mma16816(float* d, const uint32_t* a,
                                         const uint32_t* b) {
    asm volatile(
        "mma.sync.aligned.m16n8k16.row.col.f32.bf16.bf16.f32 "
        "{%0,%1,%2,%3}, {%4,%5,%6,%7}, {%8,%9}, {%0,%1,%2,%3};"
        : "+f"(d[0]), "+f"(d[1]), "+f"(d[2]), "+f"(d[3])
        : "r"(a[0]), "r"(a[1]), "r"(a[2]), "r"(a[3]), "r"(b[0]), "r"(b[1]));
}
__device__ __forceinline__ void cp16(uint32_t dst, const void* src, int sz) {
    asm volatile("cp.async.cg.shared.global [%0], [%1], 16, %2;"
                 :: "r"(dst), "l"(src), "r"(sz) : "memory");
}
#define CP_COMMIT() asm volatile("cp.async.commit_group;" ::: "memory")
#define CP_WAIT(n)  asm volatile("cp.async.wait_group %0;" :: "n"(n) : "memory")

__device__ __forceinline__ uint32_t pack2(bf16 a, bf16 b) {
    return ((uint32_t)__bfloat16_as_ushort(b) << 16) | __bfloat16_as_ushort(a);
}
__device__ __forceinline__ void split1(float v, bf16& h, bf16& l) {
    h = __float2bfloat16(v);
    l = __float2bfloat16(v - __bfloat162float(h));
}
__device__ __forceinline__ void split4(float4 v, uint2& hi, uint2& lo) {
    bf16 h0, l0, h1, l1, h2, l2, h3, l3;
    split1(v.x, h0, l0); split1(v.y, h1, l1);
    split1(v.z, h2, l2); split1(v.w, h3, l3);
    hi.x = pack2(h0, h1); hi.y = pack2(h2, h3);
    lo.x = pack2(l0, l1); lo.y = pack2(l2, l3);
}
__device__ __forceinline__ float softplus_f(float v) {
    return (v > 15.f) ? v : log1pf(__expf(v));
}
__device__ __forceinline__ float silu_f(float v) {
    return v / (1.f + __expf(-v));
}

// ---------------------------------------------------------------------------
// HMMA GEMM (NT): C[M,N] = A[M,K]·B[N,K]^T, A/B split hi+lo bf16, fp32 accum.
// CTA 128x128, K-chunk 64, double-buffered cp.async, 8 warps (64x32 each).
// EPI: 0 none, 1 softplus(acc+bias[n]), 2 acc+res[m,n].
// TRANS: 1 -> store C[col*ldc + row] (transposed output).
// ---------------------------------------------------------------------------
#define STAGE_SZ 65536
#define GEMM_SMEM (2 * STAGE_SZ)

template<int EPI, int TRANS>
__global__ void __launch_bounds__(256, 1) mma_gemm(
    const bf16* __restrict__ Ah, const bf16* __restrict__ Al, int lda,
    const bf16* __restrict__ Bh, const bf16* __restrict__ Bl, int ldb,
    float* __restrict__ C, int ldc, int N, int Ksplit, long partStride,
    const float* __restrict__ bias, const float* __restrict__ res, int ldres)
{
    extern __shared__ char smem[];
    const uint32_t sb = smem_u32(smem);
    const int tid = threadIdx.x;
    const int bRow = blockIdx.y * 128, bCol = blockIdx.x * 128;
    const int kbase = blockIdx.z * Ksplit;
    C += (long)blockIdx.z * partStride;
    const int nChunks = Ksplit >> 6;

    const int wid = tid >> 5, l = tid & 31;
    const int wm = (wid >> 2) * 64, wn = (wid & 3) * 32;

    float acc[4][4][4];
    #pragma unroll
    for (int a = 0; a < 4; a++)
        #pragma unroll
        for (int b = 0; b < 4; b++)
            #pragma unroll
            for (int c = 0; c < 4; c++) acc[a][b][c] = 0.f;

    auto loadStage = [&](int c) {
        const int kt = kbase + (c << 6);
        const uint32_t base = sb + (c & 1) * STAGE_SZ;
        #pragma unroll
        for (int it = 0; it < 4; it++) {
            int lin = it * 256 + tid;
            int row = lin >> 3, ch = lin & 7;
            uint32_t d = base + row * 128 + (((ch ^ (row & 7)) << 4));
            size_t aoff = (size_t)(bRow + row) * lda + kt + ch * 8;
            cp16(d,         Ah + aoff, 16);
            cp16(d + 16384, Al + aoff, 16);
            int bn = bCol + row;
            int ok = (bn < N) ? 16 : 0;
            size_t boff = (size_t)(bn < N ? bn : 0) * ldb + kt + ch * 8;
            cp16(d + 32768, Bh + boff, ok);
            cp16(d + 49152, Bl + boff, ok);
        }
        CP_COMMIT();
    };

    loadStage(0);
    for (int c = 0; c < nChunks; c++) {
        if (c + 1 < nChunks) { loadStage(c + 1); CP_WAIT(1); }
        else                 { CP_WAIT(0); }
        __syncthreads();
        const uint32_t st = sb + (c & 1) * STAGE_SZ;

        uint32_t baseA[4]; int r7A[4];
        #pragma unroll
        for (int mi = 0; mi < 4; mi++) {
            int r = wm + mi * 16 + (l & 15);
            baseA[mi] = st + r * 128;
            r7A[mi] = r & 7;
        }
        const int hkA = l >> 4;
        const int matb = l >> 3;
        const int rB0 = wn + (l & 7) + ((matb >> 1) << 3);
        const int hkB = matb & 1;

        #pragma unroll
        for (int ks = 0; ks < 4; ks++) {
            uint32_t Ahf[4][4], Alf[4][4], Bhf[4][2], Blf[4][2];
            #pragma unroll
            for (int mi = 0; mi < 4; mi++) {
                int ck = 2 * ks + hkA;
                uint32_t ad = baseA[mi] + ((ck ^ r7A[mi]) << 4);
                ldm_x4(Ahf[mi][0], Ahf[mi][1], Ahf[mi][2], Ahf[mi][3], ad);
                ldm_x4(Alf[mi][0], Alf[mi][1], Alf[mi][2], Alf[mi][3], ad + 16384);
            }
            #pragma unroll
            for (int ng = 0; ng < 2; ng++) {
                int r = rB0 + ng * 16;
                int ck = 2 * ks + hkB;
                uint32_t ad = st + 32768 + r * 128 + ((ck ^ (r & 7)) << 4);
                uint32_t t0, t1, t2, t3;
                ldm_x4(t0, t1, t2, t3, ad);
                Bhf[ng*2][0] = t0; Bhf[ng*2][1] = t1;
                Bhf[ng*2+1][0] = t2; Bhf[ng*2+1][1] = t3;
                ldm_x4(t0, t1, t2, t3, ad + 16384);
                Blf[ng*2][0] = t0; Blf[ng*2][1] = t1;
                Blf[ng*2+1][0] = t2; Blf[ng*2+1][1] = t3;
            }
            #pragma unroll
            for (int mi = 0; mi < 4; mi++)
                #pragma unroll
                for (int ni = 0; ni < 4; ni++) {
                    mma16816(acc[mi][ni], Ahf[mi], Bhf[ni]);
                    mma16816(acc[mi][ni], Ahf[mi], Blf[ni]);
                    mma16816(acc[mi][ni], Alf[mi], Bhf[ni]);
                }
        }
        __syncthreads();
    }

    // epilogue
    #pragma unroll
    for (int mi = 0; mi < 4; mi++) {
        #pragma unroll
        for (int h2 = 0; h2 < 2; h2++) {
            int row = bRow + wm + mi * 16 + h2 * 8 + (l >> 2);
            #pragma unroll
            for (int ni = 0; ni < 4; ni++) {
                int col = bCol + wn + ni * 8 + (l & 3) * 2;
                if (col < N) {
                    float v0 = acc[mi][ni][h2 * 2 + 0];
                    float v1 = acc[mi][ni][h2 * 2 + 1];
                    if (EPI == 1) {
                        v0 = softplus_f(v0 + bias[col]);
                        v1 = softplus_f(v1 + bias[col + 1]);
                    } else if (EPI == 2) {
                        const float* rr = res + (size_t)row * ldres + col;
                        v0 += rr[0]; v1 += rr[1];
                    }
                    if (TRANS) {
                        C[(size_t)col * ldc + row] = v0;
                        C[(size_t)(col + 1) * ldc + row] = v1;
                    } else {
                        *reinterpret_cast<float2*>(C + (size_t)row * ldc + col) =
                            make_float2(v0, v1);
                    }
                }
            }
        }
    }
}

// ---------------------------------------------------------------------------
// weight fp32 -> bf16 hi/lo
// ---------------------------------------------------------------------------
__global__ __launch_bounds__(256) void convert_w(
    const float* __restrict__ w, bf16* __restrict__ hi, bf16* __restrict__ lo,
    int n4)
{
    int i = blockIdx.x * 256 + threadIdx.x;
    if (i >= n4) return;
    float4 v = reinterpret_cast<const float4*>(w)[i];
    uint2 h, l;
    split4(v, h, l);
    reinterpret_cast<uint2*>(hi)[i] = h;
    reinterpret_cast<uint2*>(lo)[i] = l;
}

// ---------------------------------------------------------------------------
// RMSNorm -> bf16 hi/lo
// ---------------------------------------------------------------------------
__global__ __launch_bounds__(256) void rmsnorm_kernel(
    const float* __restrict__ x, const float* __restrict__ w,
    bf16* __restrict__ hh, bf16* __restrict__ hl)
{
    int row = blockIdx.x;
    int tid = threadIdx.x;
    float4 v = reinterpret_cast<const float4*>(x + (size_t)row * DMODEL)[tid];
    float ss = v.x * v.x + v.y * v.y + v.z * v.z + v.w * v.w;
    __shared__ float red[8];
    #pragma unroll
    for (int o = 16; o > 0; o >>= 1) ss += __shfl_xor_sync(0xffffffffu, ss, o);
    if ((tid & 31) == 0) red[tid >> 5] = ss;
    __syncthreads();
    if (tid < 32) {
        float t = (tid < 8) ? red[tid] : 0.f;
        #pragma unroll
        for (int o = 4; o > 0; o >>= 1) t += __shfl_xor_sync(0xffffffffu, t, o);
        if (tid == 0) red[0] = t;
    }
    __syncthreads();
    float scale = rsqrtf(red[0] * (1.0f / DMODEL) + 1e-5f);
    float4 wv = reinterpret_cast<const float4*>(w)[tid];
    float4 o;
    o.x = v.x * scale * wv.x;  o.y = v.y * scale * wv.y;
    o.z = v.z * scale * wv.z;  o.w = v.w * scale * wv.w;
    uint2 h, l;
    split4(o, h, l);
    reinterpret_cast<uint2*>(hh + (size_t)row * DMODEL)[tid] = h;
    reinterpret_cast<uint2*>(hl + (size_t)row * DMODEL)[tid] = l;
}

// ---------------------------------------------------------------------------
// conv(width4)+SiLU and silu(z): emits xs bf16 hi/lo (token-major for x_proj)
// plus xsT / gT fp32 transposed [d][tok] for the scan.
// ---------------------------------------------------------------------------
__global__ __launch_bounds__(256) void conv_silu_kernel(
    const float* __restrict__ xz,
    const float* __restrict__ conv_w, const float* __restrict__ conv_b,
    bf16* __restrict__ xsh, bf16* __restrict__ xsl,
    float* __restrict__ xsT, float* __restrict__ gT)
{
    int gid = blockIdx.x * 256 + threadIdx.x;
    if (gid >= NTOK * (DINNER / 4)) return;
    int trow = gid / (DINNER / 4);
    int d0 = (gid % (DINNER / 4)) * 4;
    int lpos = trow & (SEQ - 1);

    float4 accv = *reinterpret_cast<const float4*>(conv_b + d0);
    float* acc = &accv.x;
    #pragma unroll
    for (int k = 0; k < DCONV; k++) {
        int li = lpos + k - (DCONV - 1);
        if (li >= 0) {
            const float* xp = xz + (size_t)(trow + li - lpos) * (2 * DINNER) + d0;
            #pragma unroll
            for (int q = 0; q < 4; q++)
                acc[q] = fmaf(conv_w[(d0 + q) * DCONV + k], xp[q], acc[q]);
        }
    }
    #pragma unroll
    for (int q = 0; q < 4; q++) acc[q] = silu_f(acc[q]);
    size_t base = (size_t)trow * DINNER + d0;
    uint2 h, l;
    split4(accv, h, l);
    *reinterpret_cast<uint2*>(xsh + base) = h;
    *reinterpret_cast<uint2*>(xsl + base) = l;

    // transposed xs + gate
    float4 zv = *reinterpret_cast<const float4*>(
        xz + (size_t)trow * (2 * DINNER) + DINNER + d0);
    const float* zz = &zv.x;
    #pragma unroll
    for (int q = 0; q < 4; q++) {
        xsT[(size_t)(d0 + q) * NTOK + trow] = acc[q];
        gT[(size_t)(d0 + q) * NTOK + trow] = silu_f(zz[q]);
    }
}

// ---------------------------------------------------------------------------
// split-K reduce for x_proj -> xd bf16 hi/lo (token-major, for dt_proj) and
// B/C fp32 transposed [2*DSTATE][NTOK] for the scan.
// ---------------------------------------------------------------------------
__global__ __launch_bounds__(256) void reduce_xproj(
    const float* __restrict__ part,
    bf16* __restrict__ xdh, bf16* __restrict__ xdl,
    float* __restrict__ bcT)
{
    int idx = blockIdx.x * 256 + threadIdx.x;
    if (idx >= NTOK * XPROJ_N) return;
    float s = 0.f;
    #pragma unroll
    for (int z = 0; z < XSPLIT; z++) s += part[(size_t)z * NTOK * XPROJ_N + idx];
    bf16 h, l;
    split1(s, h, l);
    xdh[idx] = h; xdl[idx] = l;
    int row = idx / XPROJ_N, col = idx - row * XPROJ_N;
    if (col >= DTRANK)
        bcT[(size_t)(col - DTRANK) * NTOK + row] = s;
}

// ---------------------------------------------------------------------------
// selective scan + gate, all-transposed inputs, float4 per 4 steps, manual
// software pipeline. Output yT[d][t] float4 (lane 0 / 16 store).
// ---------------------------------------------------------------------------
__global__ __launch_bounds__(256) void scan_kernel(
    const float* __restrict__ dtT, const float* __restrict__ xsT,
    const float* __restrict__ bcT, const float* __restrict__ gT,
    const float* __restrict__ A_log, const float* __restrict__ Dp,
    float* __restrict__ yT)
{
    int warp = threadIdx.x >> 5;
    int lane = threadIdx.x & 31;
    int chPair = blockIdx.x * 8 + warp;
    int ch = chPair * 2 + (lane >> 4);
    int b = ch >> 11;
    int d = ch & 2047;
    int n = lane & 15;
    int rowBase = b * SEQ;

    const float* dtp = dtT + (size_t)d * NTOK + rowBase;
    const float* xsp = xsT + (size_t)d * NTOK + rowBase;
    const float* gp  = gT  + (size_t)d * NTOK + rowBase;
    const float* Bp  = bcT + (size_t)n * NTOK + rowBase;
    const float* Cp  = bcT + (size_t)(DSTATE + n) * NTOK + rowBase;
    float* yp = yT + (size_t)d * NTOK + rowBase;

    float a  = -expf(A_log[d * DSTATE + n]);
    float Dv = Dp[d];
    float s = 0.f;

    float4 dt4 = *reinterpret_cast<const float4*>(dtp);
    float4 xs4 = *reinterpret_cast<const float4*>(xsp);
    float4 g4  = *reinterpret_cast<const float4*>(gp);
    float4 B4  = *reinterpret_cast<const float4*>(Bp);
    float4 C4  = *reinterpret_cast<const float4*>(Cp);

    for (int t = 0; t < SEQ; t += 4) {
        float4 ndt, nxs, ng, nB, nC;
        if (t + 4 < SEQ) {
            ndt = *reinterpret_cast<const float4*>(dtp + t + 4);
            nxs = *reinterpret_cast<const float4*>(xsp + t + 4);
            ng  = *reinterpret_cast<const float4*>(gp + t + 4);
            nB  = *reinterpret_cast<const float4*>(Bp + t + 4);
            nC  = *reinterpret_cast<const float4*>(Cp + t + 4);
        }
        const float* dtv = &dt4.x; const float* xsv = &xs4.x;
        const float* gv = &g4.x; const float* Bv = &B4.x; const float* Cv = &C4.x;
        float4 yout;
        float* yv = &yout.x;
        #pragma unroll
        for (int q = 0; q < 4; q++) {
            float dA = __expf(dtv[q] * a);
            s = fmaf(dA, s, dtv[q] * xsv[q] * Bv[q]);
            float p = s * Cv[q];
            p += __shfl_xor_sync(0xffffffffu, p, 8);
            p += __shfl_xor_sync(0xffffffffu, p, 4);
            p += __shfl_xor_sync(0xffffffffu, p, 2);
            p += __shfl_xor_sync(0xffffffffu, p, 1);
            yv[q] = (p + Dv * xsv[q]) * gv[q];
        }
        if (n == 0)
            *reinterpret_cast<float4*>(yp + t) = yout;
        dt4 = ndt; xs4 = nxs; g4 = ng; B4 = nB; C4 = nC;
    }
}

// ---------------------------------------------------------------------------
// yT [DINNER][NTOK] fp32 -> y bf16 hi/lo [NTOK][DINNER] (tiled transpose)
// ---------------------------------------------------------------------------
__global__ __launch_bounds__(256) void transpose_split(
    const float* __restrict__ yT, bf16* __restrict__ yh, bf16* __restrict__ yl)
{
    __shared__ float tile[32][33];
    int bx = blockIdx.x, by = blockIdx.y;   // bx: tok tile, by: d tile
    int tx = threadIdx.x & 31, ty = threadIdx.x >> 5;
    #pragma unroll
    for (int j = 0; j < 32; j += 8) {
        int dd = by * 32 + ty + j;
        int tok = bx * 32 + tx;
        tile[ty + j][tx] = yT[(size_t)dd * NTOK + tok];
    }
    __syncthreads();
    #pragma unroll
    for (int j = 0; j < 32; j += 8) {
        int tok = bx * 32 + ty + j;
        int dd = by * 32 + tx;
        float v = tile[tx][ty + j];
        bf16 h, l;
        split1(v, h, l);
        yh[(size_t)tok * DINNER + dd] = h;
        yl[(size_t)tok * DINNER + dd] = l;
    }
}

// ---------------------------------------------------------------------------
// Launch
// ---------------------------------------------------------------------------
extern "C" void kernel_launch(void* const* d_in, const int* in_sizes, int n_in,
                              void* d_out, int out_size)
{
    const float* x         = (const float*)d_in[0];
    const float* norm_w    = (const float*)d_in[1];
    const float* in_proj_w = (const float*)d_in[2];
    const float* conv_w    = (const float*)d_in[3];
    const float* conv_b    = (const float*)d_in[4];
    const float* x_proj_w  = (const float*)d_in[5];
    const float* dt_proj_w = (const float*)d_in[6];
    const float* dt_proj_b = (const float*)d_in[7];
    const float* A_log     = (const float*)d_in[8];
    const float* Dp        = (const float*)d_in[9];
    const float* out_proj_w= (const float*)d_in[10];
    float* out = (float*)d_out;

    float *pxz, *pxsT, *pgT, *pdtT, *pbcT, *pyT, *ppart;
    bf16 *pwih, *pwil, *pwxh, *pwxl, *pwdh, *pwdl, *pwoh, *pwol;
    bf16 *phh, *phl, *pxsh, *pxsl, *pxdh, *pxdl, *pyh, *pyl;
    cudaGetSymbolAddress((void**)&pxz,  g_xz);
    cudaGetSymbolAddress((void**)&pxsT, g_xsT);
    cudaGetSymbolAddress((void**)&pgT,  g_gT);
    cudaGetSymbolAddress((void**)&pdtT, g_dtT);
    cudaGetSymbolAddress((void**)&pbcT, g_bcT);
    cudaGetSymbolAddress((void**)&pyT,  g_yT);
    cudaGetSymbolAddress((void**)&ppart,g_part);
    cudaGetSymbolAddress((void**)&pwih, g_wih); cudaGetSymbolAddress((void**)&pwil, g_wil);
    cudaGetSymbolAddress((void**)&pwxh, g_wxh); cudaGetSymbolAddress((void**)&pwxl, g_wxl);
    cudaGetSymbolAddress((void**)&pwdh, g_wdh); cudaGetSymbolAddress((void**)&pwdl, g_wdl);
    cudaGetSymbolAddress((void**)&pwoh, g_woh); cudaGetSymbolAddress((void**)&pwol, g_wol);
    cudaGetSymbolAddress((void**)&phh,  g_hh);  cudaGetSymbolAddress((void**)&phl,  g_hl);
    cudaGetSymbolAddress((void**)&pxsh, g_xsh); cudaGetSymbolAddress((void**)&pxsl, g_xsl);
    cudaGetSymbolAddress((void**)&pxdh, g_xdh); cudaGetSymbolAddress((void**)&pxdl, g_xdl);
    cudaGetSymbolAddress((void**)&pyh,  g_yh);  cudaGetSymbolAddress((void**)&pyl,  g_yl);

    cudaFuncSetAttribute(mma_gemm<0,0>, cudaFuncAttributeMaxDynamicSharedMemorySize, GEMM_SMEM);
    cudaFuncSetAttribute(mma_gemm<1,1>, cudaFuncAttributeMaxDynamicSharedMemorySize, GEMM_SMEM);
    cudaFuncSetAttribute(mma_gemm<2,0>, cudaFuncAttributeMaxDynamicSharedMemorySize, GEMM_SMEM);

    // 0) weight conversion
    convert_w<<<(2*DINNER*DMODEL/4 + 255)/256, 256>>>(in_proj_w,  pwih, pwil, 2*DINNER*DMODEL/4);
    convert_w<<<(XPROJ_N*DINNER/4 + 255)/256, 256>>>(x_proj_w,   pwxh, pwxl, XPROJ_N*DINNER/4);
    convert_w<<<(DINNER*DTRANK/4 + 255)/256, 256>>>(dt_proj_w,  pwdh, pwdl, DINNER*DTRANK/4);
    convert_w<<<(DMODEL*DINNER/4 + 255)/256, 256>>>(out_proj_w, pwoh, pwol, DMODEL*DINNER/4);

    // 1) RMSNorm
    rmsnorm_kernel<<<NTOK, 256>>>(x, norm_w, phh, phl);

    // 2) in_proj
    {
        dim3 grid((2 * DINNER) / 128, NTOK / 128, 1);
        mma_gemm<0,0><<<grid, 256, GEMM_SMEM>>>(
            phh, phl, DMODEL, pwih, pwil, DMODEL,
            pxz, 2 * DINNER, 2 * DINNER, DMODEL, 0, nullptr, nullptr, 0);
    }

    // 3) conv + silu (+ transposed xs, gate)
    conv_silu_kernel<<<(NTOK * DINNER / 4) / 256, 256>>>(
        pxz, conv_w, conv_b, pxsh, pxsl, pxsT, pgT);

    // 4) x_proj split-K
    {
        dim3 grid(1, NTOK / 128, XSPLIT);
        mma_gemm<0,0><<<grid, 256, GEMM_SMEM>>>(
            pxsh, pxsl, DINNER, pwxh, pwxl, DINNER,
            ppart, XPROJ_N, XPROJ_N, DINNER / XSPLIT,
            (long)NTOK * XPROJ_N, nullptr, nullptr, 0);
    }
    reduce_xproj<<<(NTOK * XPROJ_N + 255) / 256, 256>>>(ppart, pxdh, pxdl, pbcT);

    // 5) dt_proj + softplus, transposed store -> dtT
    {
        dim3 grid(DINNER / 128, NTOK / 128, 1);
        mma_gemm<1,1><<<grid, 256, GEMM_SMEM>>>(
            pxdh, pxdl, XPROJ_N, pwdh, pwdl, DTRANK,
            pdtT, NTOK, DINNER, DTRANK, 0, dt_proj_b, nullptr, 0);
    }

    // 6) scan -> yT
    scan_kernel<<<(BATCH * DINNER) / 16, 256>>>(pdtT, pxsT, pbcT, pgT,
                                                A_log, Dp, pyT);

    // 7) transpose + split y
    {
        dim3 grid(NTOK / 32, DINNER / 32);
        transpose_split<<<grid, 256>>>(pyT, pyh, pyl);
    }

    // 8) out_proj + residual
    {
        dim3 grid(DMODEL / 128, NTOK / 128, 1);
        mma_gemm<2,0><<<grid, 256, GEMM_SMEM>>>(
            pyh, pyl, DINNER, pwoh, pwol, DINNER,
            out, DMODEL, DMODEL, DINNER, 0, nullptr, x, DMODEL);
    }
}